// round 1
// baseline (speedup 1.0000x reference)
#include <cuda_runtime.h>

// Problem constants
#define NUM_E   64
#define IN_F    512
#define OUT_F   512
#define NTOK    131072
#define CAPACITY 3072

// GEMM tile config
#define TM 128
#define TN 128
#define TK 16
#define TW (TM + 4)   // padded smem row to dodge bank conflicts on transposed store

__device__ int g_cnt[NUM_E];
__device__ int g_perm[NUM_E * CAPACITY];

__global__ void k_zero() {
    if (threadIdx.x < NUM_E) g_cnt[threadIdx.x] = 0;
}

// Bucket tokens per expert (fixed-capacity layout: no prefix scan needed).
// Overflow tokens (rank >= CAPACITY) get a zero output row, matching the
// reference's trash-row semantics. Never triggers for this distribution.
__global__ void k_scatter(const int* __restrict__ eid, float* __restrict__ out) {
    int t = blockIdx.x * blockDim.x + threadIdx.x;
    if (t >= NTOK) return;
    int e = eid[t];
    int r = atomicAdd(&g_cnt[e], 1);
    if (r < CAPACITY) {
        g_perm[e * CAPACITY + r] = t;
    } else {
        float4* o = (float4*)(out + (long long)t * OUT_F);
        float4 z = make_float4(0.f, 0.f, 0.f, 0.f);
        #pragma unroll 4
        for (int i = 0; i < OUT_F / 4; i++) o[i] = z;
    }
}

// Per-expert GEMM: Y[c, o] = X[perm[c], :] . W[e][o, :] + bias[e][o]
// Grid: x = (CAPACITY/TM) * (OUT_F/TN) = 24*4, y = expert.
// A rows gathered via g_perm; C rows scattered to out[token].
__global__ __launch_bounds__(256, 2)
void k_gemm(const float* __restrict__ x, const float* __restrict__ w,
            const float* __restrict__ bias, float* __restrict__ out) {
    __shared__ float As[2][TK][TW];
    __shared__ float Bs[2][TK][TW];

    const int e   = blockIdx.y;
    const int cnt = g_cnt[e];
    const int m0  = (blockIdx.x >> 2) * TM;
    if (m0 >= cnt) return;                    // empty token tile
    const int n0  = (blockIdx.x & 3) * TN;

    const int tid = threadIdx.x;
    const int* __restrict__ perm = g_perm + e * CAPACITY + m0;

    // Loader mapping: 512 float4 slots per operand, 2 per thread.
    const int rowA0 = tid >> 2;          // 0..63
    const int rowA1 = rowA0 + 64;        // 64..127
    const int kq    = (tid & 3) << 2;    // k offset within TK slab: 0,4,8,12

    const bool v0 = (m0 + rowA0 < cnt);
    const bool v1 = (m0 + rowA1 < cnt);
    const int tok0 = v0 ? perm[rowA0] : 0;
    const int tok1 = v1 ? perm[rowA1] : 0;

    const float* __restrict__ xA0 = x + (long long)tok0 * IN_F + kq;
    const float* __restrict__ xA1 = x + (long long)tok1 * IN_F + kq;
    const float* __restrict__ wBase = w + (long long)e * OUT_F * IN_F
                                        + (long long)n0 * IN_F + kq;
    const float* __restrict__ wB0 = wBase + (long long)rowA0 * IN_F;
    const float* __restrict__ wB1 = wBase + (long long)rowA1 * IN_F;

    // Compute mapping: 16x16 thread grid, each thread 8x8 outputs.
    const int m_t = (tid >> 4) << 3;
    const int n_t = (tid & 15) << 3;

    float acc[8][8];
    #pragma unroll
    for (int i = 0; i < 8; i++)
        #pragma unroll
        for (int j = 0; j < 8; j++) acc[i][j] = 0.f;

    const float4 z4 = make_float4(0.f, 0.f, 0.f, 0.f);

    // --- prologue: load K-slab 0 into buffer 0 ---
    float4 va0 = v0 ? *(const float4*)(xA0) : z4;
    float4 va1 = v1 ? *(const float4*)(xA1) : z4;
    float4 vb0 = *(const float4*)(wB0);
    float4 vb1 = *(const float4*)(wB1);

    As[0][kq + 0][rowA0] = va0.x; As[0][kq + 1][rowA0] = va0.y;
    As[0][kq + 2][rowA0] = va0.z; As[0][kq + 3][rowA0] = va0.w;
    As[0][kq + 0][rowA1] = va1.x; As[0][kq + 1][rowA1] = va1.y;
    As[0][kq + 2][rowA1] = va1.z; As[0][kq + 3][rowA1] = va1.w;
    Bs[0][kq + 0][rowA0] = vb0.x; Bs[0][kq + 1][rowA0] = vb0.y;
    Bs[0][kq + 2][rowA0] = vb0.z; Bs[0][kq + 3][rowA0] = vb0.w;
    Bs[0][kq + 0][rowA1] = vb1.x; Bs[0][kq + 1][rowA1] = vb1.y;
    Bs[0][kq + 2][rowA1] = vb1.z; Bs[0][kq + 3][rowA1] = vb1.w;
    __syncthreads();

    int buf = 0;
    for (int k0 = TK; k0 <= IN_F; k0 += TK) {
        const bool more = (k0 < IN_F);
        if (more) {  // prefetch next slab into registers
            va0 = v0 ? *(const float4*)(xA0 + k0) : z4;
            va1 = v1 ? *(const float4*)(xA1 + k0) : z4;
            vb0 = *(const float4*)(wB0 + k0);
            vb1 = *(const float4*)(wB1 + k0);
        }

        #pragma unroll
        for (int kk = 0; kk < TK; kk++) {
            float4 a0 = *(const float4*)&As[buf][kk][m_t];
            float4 a1 = *(const float4*)&As[buf][kk][m_t + 4];
            float4 b0 = *(const float4*)&Bs[buf][kk][n_t];
            float4 b1 = *(const float4*)&Bs[buf][kk][n_t + 4];
            float a[8] = {a0.x, a0.y, a0.z, a0.w, a1.x, a1.y, a1.z, a1.w};
            float b[8] = {b0.x, b0.y, b0.z, b0.w, b1.x, b1.y, b1.z, b1.w};
            #pragma unroll
            for (int i = 0; i < 8; i++)
                #pragma unroll
                for (int j = 0; j < 8; j++)
                    acc[i][j] += a[i] * b[j];
        }

        if (more) {  // stage prefetched regs into the other buffer
            buf ^= 1;
            As[buf][kq + 0][rowA0] = va0.x; As[buf][kq + 1][rowA0] = va0.y;
            As[buf][kq + 2][rowA0] = va0.z; As[buf][kq + 3][rowA0] = va0.w;
            As[buf][kq + 0][rowA1] = va1.x; As[buf][kq + 1][rowA1] = va1.y;
            As[buf][kq + 2][rowA1] = va1.z; As[buf][kq + 3][rowA1] = va1.w;
            Bs[buf][kq + 0][rowA0] = vb0.x; Bs[buf][kq + 1][rowA0] = vb0.y;
            Bs[buf][kq + 2][rowA0] = vb0.z; Bs[buf][kq + 3][rowA0] = vb0.w;
            Bs[buf][kq + 0][rowA1] = vb1.x; Bs[buf][kq + 1][rowA1] = vb1.y;
            Bs[buf][kq + 2][rowA1] = vb1.z; Bs[buf][kq + 3][rowA1] = vb1.w;
            __syncthreads();
        }
    }

    // --- epilogue: bias + scatter rows back to out[token] ---
    float bv[8];
    #pragma unroll
    for (int j = 0; j < 8; j++)
        bv[j] = bias[e * OUT_F + n0 + n_t + j];

    #pragma unroll
    for (int i = 0; i < 8; i++) {
        const int row = m_t + i;
        if (m0 + row < cnt) {
            const int tok = perm[row];
            float* op = out + (long long)tok * OUT_F + n0 + n_t;
            float4 r0 = make_float4(acc[i][0] + bv[0], acc[i][1] + bv[1],
                                    acc[i][2] + bv[2], acc[i][3] + bv[3]);
            float4 r1 = make_float4(acc[i][4] + bv[4], acc[i][5] + bv[5],
                                    acc[i][6] + bv[6], acc[i][7] + bv[7]);
            *(float4*)op       = r0;
            *(float4*)(op + 4) = r1;
        }
    }
}

extern "C" void kernel_launch(void* const* d_in, const int* in_sizes, int n_in,
                              void* d_out, int out_size) {
    const float* x    = (const float*)d_in[0];
    const float* wght = (const float*)d_in[1];
    const float* bias = (const float*)d_in[2];
    const int*   eid  = (const int*)d_in[3];
    float* out = (float*)d_out;

    k_zero<<<1, 64>>>();
    k_scatter<<<(NTOK + 255) / 256, 256>>>(eid, out);

    dim3 grid((CAPACITY / TM) * (OUT_F / TN), NUM_E);
    k_gemm<<<grid, 256>>>(x, wght, bias, out);
}

// round 3
// speedup vs baseline: 1.6152x; 1.6152x over previous
#include <cuda_runtime.h>
#include <cuda_bf16.h>
#include <cstdint>

// ---------------- problem constants ----------------
#define NUM_E    64
#define IN_F     512
#define OUT_F    512
#define NTOK     131072
#define CAPACITY 3072

// ---------------- tiling ----------------
#define TM 128
#define TN 128
#define KC 64                  // K chunk (bf16 row = 128B)
#define NCH (IN_F / KC)        // 8
#define THREADS 512

// ---------------- smem layout (bytes) ----------------
#define SM_TOK   0                       // 128 ints
#define SM_BIAS  512                     // 128 floats
#define SM_BUF   1024                    // bf16 tiles: AH, AL, BH, BL
#define TILE_SZ  (128 * 64 * 2)          // 16384
#define OFF_AH   0
#define OFF_AL   TILE_SZ
#define OFF_BH   (2 * TILE_SZ)
#define OFF_BL   (3 * TILE_SZ)
#define SM_STAGE (SM_BUF + 4 * TILE_SZ)  // 66560: fp32 staging, 2 stages
#define STAGE_SZ 65536                   // A 32K + B 32K per stage
#define SMEM_TOTAL (SM_STAGE + 2 * STAGE_SZ)  // 197632

#define ACCW 132                          // padded fp32 acc row stride (floats)

// swizzle: for 128B rows, SWZ(row*128+c) = row*128 + (c ^ ((row&7)*16))
#define SWZ(off) ((off) ^ (((off) >> 3) & 0x70))

__device__ int g_cnt[NUM_E];
__device__ int g_perm[NUM_E * CAPACITY];

// ---------------- PTX helpers ----------------
__device__ __forceinline__ uint32_t smem_u32(const void* p) {
    uint32_t a;
    asm("{ .reg .u64 t; cvta.to.shared.u64 t, %1; cvt.u32.u64 %0, t; }"
        : "=r"(a) : "l"(p));
    return a;
}
__device__ __forceinline__ void cp16(uint32_t dst, const void* src) {
    asm volatile("cp.async.cg.shared.global [%0], [%1], 16;"
                 :: "r"(dst), "l"(src));
}
__device__ __forceinline__ void cp_commit() {
    asm volatile("cp.async.commit_group;" ::: "memory");
}
__device__ __forceinline__ void cp_wait1() {
    asm volatile("cp.async.wait_group 1;" ::: "memory");
}
__device__ __forceinline__ void cp_wait0() {
    asm volatile("cp.async.wait_group 0;" ::: "memory");
}
__device__ __forceinline__ void ldsm4(uint32_t* r, uint32_t a) {
    asm volatile("ldmatrix.sync.aligned.m8n8.x4.shared.b16 {%0,%1,%2,%3}, [%4];"
                 : "=r"(r[0]), "=r"(r[1]), "=r"(r[2]), "=r"(r[3]) : "r"(a));
}
__device__ __forceinline__ void mma16816(float* d, const uint32_t* a,
                                         const uint32_t* b) {
    asm volatile(
        "mma.sync.aligned.m16n8k16.row.col.f32.bf16.bf16.f32 "
        "{%0,%1,%2,%3}, {%4,%5,%6,%7}, {%8,%9}, {%0,%1,%2,%3};"
        : "+f"(d[0]), "+f"(d[1]), "+f"(d[2]), "+f"(d[3])
        : "r"(a[0]), "r"(a[1]), "r"(a[2]), "r"(a[3]), "r"(b[0]), "r"(b[1]));
}

// ---------------- routing ----------------
__global__ void k_zero() {
    if (threadIdx.x < NUM_E) g_cnt[threadIdx.x] = 0;
}

__global__ void k_scatter(const int* __restrict__ eid, float* __restrict__ out) {
    int t = blockIdx.x * blockDim.x + threadIdx.x;
    if (t >= NTOK) return;
    int e = eid[t];
    int r = atomicAdd(&g_cnt[e], 1);
    if (r < CAPACITY) {
        g_perm[e * CAPACITY + r] = t;
    } else {
        float4* o = (float4*)(out + (size_t)t * OUT_F);
        float4 z = make_float4(0.f, 0.f, 0.f, 0.f);
        #pragma unroll 4
        for (int i = 0; i < OUT_F / 4; i++) o[i] = z;
    }
}

// fp32 -> bf16 hi/lo split of 8 elems; swizzled 16B stores
__device__ __forceinline__ void cvt8_store(char* hi, char* lo, uint32_t off,
                                           const float* src) {
    float4 v0 = *(const float4*)src;
    float4 v1 = *(const float4*)(src + 4);
    float f[8] = {v0.x, v0.y, v0.z, v0.w, v1.x, v1.y, v1.z, v1.w};
    uint32_t H[4], L[4];
#pragma unroll
    for (int j = 0; j < 4; j++) {
        __nv_bfloat16 h0 = __float2bfloat16(f[2 * j]);
        __nv_bfloat16 h1 = __float2bfloat16(f[2 * j + 1]);
        __nv_bfloat16 l0 = __float2bfloat16(f[2 * j]     - __bfloat162float(h0));
        __nv_bfloat16 l1 = __float2bfloat16(f[2 * j + 1] - __bfloat162float(h1));
        H[j] = ((uint32_t)__bfloat16_as_ushort(h1) << 16) | __bfloat16_as_ushort(h0);
        L[j] = ((uint32_t)__bfloat16_as_ushort(l1) << 16) | __bfloat16_as_ushort(l0);
    }
    *(uint4*)(hi + off) = make_uint4(H[0], H[1], H[2], H[3]);
    *(uint4*)(lo + off) = make_uint4(L[0], L[1], L[2], L[3]);
}

// ---------------- main GEMM ----------------
__global__ __launch_bounds__(THREADS, 1)
void k_gemm(const float* __restrict__ x, const float* __restrict__ w,
            const float* __restrict__ bias, float* __restrict__ out) {
    extern __shared__ char smem[];

    const int e = blockIdx.y;
    int cnt = g_cnt[e];
    if (cnt > CAPACITY) cnt = CAPACITY;
    const int m0 = (blockIdx.x >> 2) * TM;
    if (m0 >= cnt) return;
    const int n0 = (blockIdx.x & 3) * TN;

    const int tid  = threadIdx.x;
    const int lane = tid & 31;
    const int wid  = tid >> 5;

    int*   stok  = (int*)(smem + SM_TOK);
    float* sbias = (float*)(smem + SM_BIAS);

    if (tid < TM) {
        stok[tid] = g_perm[e * CAPACITY + m0 + ((m0 + tid < cnt) ? tid : 0)];
    } else if (tid < 2 * TM) {
        sbias[tid - TM] = bias[e * OUT_F + n0 + (tid - TM)];
    }
    __syncthreads();

    const uint32_t sb = smem_u32(smem);
    const float* wbase = w + ((size_t)e * OUT_F + n0) * IN_F;

    // --- cp.async issue of chunk c into stage st ---
    auto issue = [&](int c, int st) {
        const uint32_t stA = sb + SM_STAGE + st * STAGE_SZ;
        const uint32_t stB = stA + 32768;
        const int k0 = c * KC;
#pragma unroll
        for (int i = 0; i < 4; i++) {
            int g = tid + i * THREADS;          // 0..2047
            int row = g >> 4, c4 = g & 15;      // 16 float4 per row
            cp16(stA + row * 256 + c4 * 16,
                 x + (size_t)stok[row] * IN_F + k0 + c4 * 4);
            cp16(stB + row * 256 + c4 * 16,
                 wbase + (size_t)row * IN_F + k0 + c4 * 4);
        }
        cp_commit();
    };

    // --- convert stage st -> swizzled bf16 hi/lo tiles ---
    auto convert = [&](int st) {
        char* stA = smem + SM_STAGE + st * STAGE_SZ;
        char* stB = stA + 32768;
        char* bufA = smem + SM_BUF;
        char* bufB = smem + SM_BUF + OFF_BH;
#pragma unroll
        for (int i = 0; i < 2; i++) {
            int g = tid + i * THREADS;          // 0..1023
            int row = g >> 3, kg = g & 7;
            uint32_t off = SWZ((uint32_t)(row * 128 + kg * 16));
            cvt8_store(bufA, bufA + TILE_SZ, off,
                       (const float*)(stA + row * 256 + kg * 32));
            cvt8_store(bufB, bufB + TILE_SZ, off,
                       (const float*)(stB + row * 256 + kg * 32));
        }
    };

    // --- per-warp ldmatrix address precompute ---
    const int aw = (wid & 3) * 32;   // warp M offset
    const int bw = (wid >> 2) * 32;  // warp N offset

    uint32_t a_base[2], a_mask[2];
    {
        int ar = lane & 15;
#pragma unroll
        for (int fi = 0; fi < 2; fi++) {
            int r = aw + fi * 16 + ar;
            a_base[fi] = sb + SM_BUF + OFF_AH + r * 128;
            a_mask[fi] = (r & 7) * 16;
        }
    }
    const uint32_t a_klane = (lane & 16) ? 16u : 0u;

    uint32_t b_base[2], b_mask[2];
    {
        int br = (lane & 7) + ((lane & 16) ? 8 : 0);
#pragma unroll
        for (int jp = 0; jp < 2; jp++) {
            int r = bw + jp * 16 + br;
            b_base[jp] = sb + SM_BUF + OFF_BH + r * 128;
            b_mask[jp] = (r & 7) * 16;
        }
    }
    const uint32_t b_klane = (lane & 8) ? 16u : 0u;

    float acc[2][4][4];
#pragma unroll
    for (int i = 0; i < 2; i++)
#pragma unroll
        for (int j = 0; j < 4; j++)
#pragma unroll
            for (int q = 0; q < 4; q++) acc[i][j][q] = 0.f;

    // --- pipeline ---
    issue(0, 0);
    issue(1, 1);

    for (int c = 0; c < NCH; c++) {
        if (c == NCH - 1) cp_wait0(); else cp_wait1();
        __syncthreads();
        convert(c & 1);
        __syncthreads();
        if (c + 2 < NCH) issue(c + 2, c & 1);

        // compute: 4 K=16 steps on the bf16 tiles
#pragma unroll
        for (int s = 0; s < 4; s++) {
            uint32_t ah[2][4], al[2][4], bh[2][4], bl[2][4];
            const uint32_t kcol = (uint32_t)(s * 32);
#pragma unroll
            for (int fi = 0; fi < 2; fi++) {
                uint32_t ad = a_base[fi] + ((kcol + a_klane) ^ a_mask[fi]);
                ldsm4(ah[fi], ad);
                ldsm4(al[fi], ad + TILE_SZ);
            }
#pragma unroll
            for (int jp = 0; jp < 2; jp++) {
                uint32_t bd = b_base[jp] + ((kcol + b_klane) ^ b_mask[jp]);
                ldsm4(bh[jp], bd);
                ldsm4(bl[jp], bd + TILE_SZ);
            }
#pragma unroll
            for (int fi = 0; fi < 2; fi++) {
#pragma unroll
                for (int j = 0; j < 4; j++) {
                    const uint32_t* Bh = &bh[j >> 1][(j & 1) * 2];
                    const uint32_t* Bl = &bl[j >> 1][(j & 1) * 2];
                    mma16816(acc[fi][j], ah[fi], Bh);
                    mma16816(acc[fi][j], ah[fi], Bl);
                    mma16816(acc[fi][j], al[fi], Bh);
                }
            }
        }
    }

    // --- epilogue: stage acc through smem for coalesced scatter ---
    __syncthreads();   // everyone done with bufs/stages
    float* sacc = (float*)(smem + SM_STAGE);
    {
        const int r0 = aw + (lane >> 2);
        const int c0 = bw + 2 * (lane & 3);
#pragma unroll
        for (int fi = 0; fi < 2; fi++) {
#pragma unroll
            for (int j = 0; j < 4; j++) {
                int rr = r0 + fi * 16;
                int cc = c0 + j * 8;
                sacc[rr * ACCW + cc]           = acc[fi][j][0];
                sacc[rr * ACCW + cc + 1]       = acc[fi][j][1];
                sacc[(rr + 8) * ACCW + cc]     = acc[fi][j][2];
                sacc[(rr + 8) * ACCW + cc + 1] = acc[fi][j][3];
            }
        }
    }
    __syncthreads();

    {
        const int row = tid >> 2;
        const int q   = (tid & 3) * 32;
        if (m0 + row < cnt) {
            const int tok = stok[row];
            float* op = out + (size_t)tok * OUT_F + n0 + q;
            const float* sr = &sacc[row * ACCW + q];
#pragma unroll
            for (int i = 0; i < 8; i++) {
                float4 v = *(const float4*)(sr + i * 4);
                v.x += sbias[q + i * 4 + 0];
                v.y += sbias[q + i * 4 + 1];
                v.z += sbias[q + i * 4 + 2];
                v.w += sbias[q + i * 4 + 3];
                *(float4*)(op + i * 4) = v;
            }
        }
    }
}

// ---------------- launch ----------------
extern "C" void kernel_launch(void* const* d_in, const int* in_sizes, int n_in,
                              void* d_out, int out_size) {
    const float* x    = (const float*)d_in[0];
    const float* wght = (const float*)d_in[1];
    const float* bias = (const float*)d_in[2];
    const int*   eid  = (const int*)d_in[3];
    float* out = (float*)d_out;

    static int configured = 0;
    cudaFuncSetAttribute(k_gemm, cudaFuncAttributeMaxDynamicSharedMemorySize,
                         SMEM_TOTAL);
    (void)configured;

    k_zero<<<1, 64>>>();
    k_scatter<<<(NTOK + 255) / 256, 256>>>(eid, out);

    dim3 grid((CAPACITY / TM) * (OUT_F / TN), NUM_E);
    k_gemm<<<grid, THREADS, SMEM_TOTAL>>>(x, wght, bias, out);
}

// round 4
// speedup vs baseline: 2.0763x; 1.2855x over previous
#include <cuda_runtime.h>
#include <cuda_bf16.h>
#include <cstdint>

// ---------------- problem constants ----------------
#define NUM_E    64
#define IN_F     512
#define OUT_F    512
#define NTOK     131072
#define CAPACITY 3072

// ---------------- tiling ----------------
#define TM 128
#define TN 128
#define KC 64                  // K chunk (64 bf16 = 128B row)
#define NCH (IN_F / KC)        // 8
#define THREADS 512
#define NSTAGE 3

// ---------------- smem layout (bytes) ----------------
#define SM_TOK   0                       // 128 ints
#define SM_BIAS  512                     // 128 floats
#define SM_BUF   1024
#define TILE_SZ  (128 * 64 * 2)          // 16384 per tile
#define STG_SZ   (4 * TILE_SZ)           // 65536: AH, AL, BH, BL
#define SMEM_TOTAL (SM_BUF + NSTAGE * STG_SZ)   // 197632

#define ACCW 132                          // padded epilogue stride (floats)

#define SWZ(off) ((off) ^ (((off) >> 3) & 0x70))

__device__ int g_cnt[NUM_E];
__device__ int g_perm[NUM_E * CAPACITY];

// preconverted bf16 hi/lo operands
__device__ __nv_bfloat16 g_xh[(size_t)NTOK * IN_F];          // 128 MB
__device__ __nv_bfloat16 g_xl[(size_t)NTOK * IN_F];          // 128 MB
__device__ __nv_bfloat16 g_wh[(size_t)NUM_E * OUT_F * IN_F]; // 32 MB
__device__ __nv_bfloat16 g_wl[(size_t)NUM_E * OUT_F * IN_F]; // 32 MB

// ---------------- PTX helpers ----------------
__device__ __forceinline__ uint32_t smem_u32(const void* p) {
    uint32_t a;
    asm("{ .reg .u64 t; cvta.to.shared.u64 t, %1; cvt.u32.u64 %0, t; }"
        : "=r"(a) : "l"(p));
    return a;
}
__device__ __forceinline__ void cp16(uint32_t dst, const void* src) {
    asm volatile("cp.async.cg.shared.global [%0], [%1], 16;"
                 :: "r"(dst), "l"(src));
}
__device__ __forceinline__ void cp_commit() {
    asm volatile("cp.async.commit_group;" ::: "memory");
}
template <int N>
__device__ __forceinline__ void cp_wait() {
    asm volatile("cp.async.wait_group %0;" :: "n"(N) : "memory");
}
__device__ __forceinline__ void ldsm4(uint32_t* r, uint32_t a) {
    asm volatile("ldmatrix.sync.aligned.m8n8.x4.shared.b16 {%0,%1,%2,%3}, [%4];"
                 : "=r"(r[0]), "=r"(r[1]), "=r"(r[2]), "=r"(r[3]) : "r"(a));
}
__device__ __forceinline__ void mma16816(float* d, const uint32_t* a,
                                         const uint32_t* b) {
    asm volatile(
        "mma.sync.aligned.m16n8k16.row.col.f32.bf16.bf16.f32 "
        "{%0,%1,%2,%3}, {%4,%5,%6,%7}, {%8,%9}, {%0,%1,%2,%3};"
        : "+f"(d[0]), "+f"(d[1]), "+f"(d[2]), "+f"(d[3])
        : "r"(a[0]), "r"(a[1]), "r"(a[2]), "r"(a[3]), "r"(b[0]), "r"(b[1]));
}

// ---------------- routing ----------------
__global__ void k_zero() {
    if (threadIdx.x < NUM_E) g_cnt[threadIdx.x] = 0;
}

__global__ void k_scatter(const int* __restrict__ eid, float* __restrict__ out) {
    int t = blockIdx.x * blockDim.x + threadIdx.x;
    if (t >= NTOK) return;
    int e = eid[t];
    int r = atomicAdd(&g_cnt[e], 1);
    if (r < CAPACITY) {
        g_perm[e * CAPACITY + r] = t;
    } else {
        float4* o = (float4*)(out + (size_t)t * OUT_F);
        float4 z = make_float4(0.f, 0.f, 0.f, 0.f);
        #pragma unroll 4
        for (int i = 0; i < OUT_F / 4; i++) o[i] = z;
    }
}

// ---------------- fp32 -> bf16 hi/lo pre-pass (bandwidth bound) ----------------
__global__ __launch_bounds__(256)
void k_cvt(const float* __restrict__ src, __nv_bfloat16* __restrict__ hi,
           __nv_bfloat16* __restrict__ lo, int n8) {
    int g = blockIdx.x * blockDim.x + threadIdx.x;
    if (g >= n8) return;
    const float4 v0 = *(const float4*)(src + (size_t)g * 8);
    const float4 v1 = *(const float4*)(src + (size_t)g * 8 + 4);
    float f[8] = {v0.x, v0.y, v0.z, v0.w, v1.x, v1.y, v1.z, v1.w};
    uint32_t H[4], L[4];
#pragma unroll
    for (int j = 0; j < 4; j++) {
        __nv_bfloat16 h0 = __float2bfloat16(f[2 * j]);
        __nv_bfloat16 h1 = __float2bfloat16(f[2 * j + 1]);
        __nv_bfloat16 l0 = __float2bfloat16(f[2 * j]     - __bfloat162float(h0));
        __nv_bfloat16 l1 = __float2bfloat16(f[2 * j + 1] - __bfloat162float(h1));
        H[j] = ((uint32_t)__bfloat16_as_ushort(h1) << 16) | __bfloat16_as_ushort(h0);
        L[j] = ((uint32_t)__bfloat16_as_ushort(l1) << 16) | __bfloat16_as_ushort(l0);
    }
    *(uint4*)(hi + (size_t)g * 8) = make_uint4(H[0], H[1], H[2], H[3]);
    *(uint4*)(lo + (size_t)g * 8) = make_uint4(L[0], L[1], L[2], L[3]);
}

// ---------------- main GEMM (MMA-only mainloop) ----------------
__global__ __launch_bounds__(THREADS, 1)
void k_gemm(const float* __restrict__ bias, float* __restrict__ out) {
    extern __shared__ char smem[];

    const int e = blockIdx.y;
    int cnt = g_cnt[e];
    if (cnt > CAPACITY) cnt = CAPACITY;
    const int m0 = (blockIdx.x >> 2) * TM;
    if (m0 >= cnt) return;
    const int n0 = (blockIdx.x & 3) * TN;

    const int tid  = threadIdx.x;
    const int lane = tid & 31;
    const int wid  = tid >> 5;

    int*   stok  = (int*)(smem + SM_TOK);
    float* sbias = (float*)(smem + SM_BIAS);

    if (tid < TM) {
        stok[tid] = g_perm[e * CAPACITY + m0 + ((m0 + tid < cnt) ? tid : 0)];
    } else if (tid < 2 * TM) {
        sbias[tid - TM] = bias[e * OUT_F + n0 + (tid - TM)];
    }
    __syncthreads();

    const uint32_t sb = smem_u32(smem);
    const size_t wrow0 = ((size_t)e * OUT_F + n0) * IN_F;

    // per-thread cp.async mapping: 4096 chunks of 16B per stage, 8 per thread
    // g = tid + i*512 : tile = g>>10 (0:AH 1:AL 2:BH 3:BL), row=(g>>3)&127, kg=g&7
    auto issue = [&](int c, int st) {
        const uint32_t stg = sb + SM_BUF + st * STG_SZ;
        const int k0 = c * KC;
#pragma unroll
        for (int i = 0; i < 8; i++) {
            int g = tid + i * THREADS;
            int tile = g >> 10, row = (g >> 3) & 127, kg = g & 7;
            uint32_t dst = stg + tile * TILE_SZ + SWZ((uint32_t)(row * 128 + kg * 16));
            const __nv_bfloat16* src;
            if (tile < 2) {
                const __nv_bfloat16* base = tile ? g_xl : g_xh;
                src = base + (size_t)stok[row] * IN_F + k0 + kg * 8;
            } else {
                const __nv_bfloat16* base = (tile == 2) ? g_wh : g_wl;
                src = base + wrow0 + (size_t)row * IN_F + k0 + kg * 8;
            }
            cp16(dst, src);
        }
        cp_commit();
    };

    // per-warp ldmatrix address precompute (stage-relative)
    const int aw = (wid & 3) * 32;   // warp M offset
    const int bw = (wid >> 2) * 32;  // warp N offset

    uint32_t a_off[2], a_mask[2];
    {
        int ar = lane & 15;
#pragma unroll
        for (int fi = 0; fi < 2; fi++) {
            int r = aw + fi * 16 + ar;
            a_off[fi] = (uint32_t)(r * 128);
            a_mask[fi] = (r & 7) * 16;
        }
    }
    const uint32_t a_klane = (lane & 16) ? 16u : 0u;

    uint32_t b_off[2], b_mask[2];
    {
        int br = (lane & 7) + ((lane & 16) ? 8 : 0);
#pragma unroll
        for (int jp = 0; jp < 2; jp++) {
            int r = bw + jp * 16 + br;
            b_off[jp] = (uint32_t)(2 * TILE_SZ + r * 128);
            b_mask[jp] = (r & 7) * 16;
        }
    }
    const uint32_t b_klane = (lane & 8) ? 16u : 0u;

    float acc[2][4][4];
#pragma unroll
    for (int i = 0; i < 2; i++)
#pragma unroll
        for (int j = 0; j < 4; j++)
#pragma unroll
            for (int q = 0; q < 4; q++) acc[i][j][q] = 0.f;

    // ---- pipeline: 3 stages in flight ----
    issue(0, 0);
    issue(1, 1);
    issue(2, 2);

#pragma unroll
    for (int c = 0; c < NCH; c++) {
        if (c <= NCH - 3)      cp_wait<2>();
        else if (c == NCH - 2) cp_wait<1>();
        else                   cp_wait<0>();
        __syncthreads();

        const uint32_t stg = sb + SM_BUF + (c % NSTAGE) * STG_SZ;

#pragma unroll
        for (int s = 0; s < 4; s++) {
            uint32_t ah[2][4], al[2][4], bh[2][4], bl[2][4];
            const uint32_t kcol = (uint32_t)(s * 32);
#pragma unroll
            for (int fi = 0; fi < 2; fi++) {
                uint32_t ad = stg + a_off[fi] + ((kcol + a_klane) ^ a_mask[fi]);
                ldsm4(ah[fi], ad);
                ldsm4(al[fi], ad + TILE_SZ);
            }
#pragma unroll
            for (int jp = 0; jp < 2; jp++) {
                uint32_t bd = stg + b_off[jp] + ((kcol + b_klane) ^ b_mask[jp]);
                ldsm4(bh[jp], bd);
                ldsm4(bl[jp], bd + TILE_SZ);
            }
#pragma unroll
            for (int fi = 0; fi < 2; fi++) {
#pragma unroll
                for (int j = 0; j < 4; j++) {
                    const uint32_t* Bh = &bh[j >> 1][(j & 1) * 2];
                    const uint32_t* Bl = &bl[j >> 1][(j & 1) * 2];
                    mma16816(acc[fi][j], ah[fi], Bh);
                    mma16816(acc[fi][j], ah[fi], Bl);
                    mma16816(acc[fi][j], al[fi], Bh);
                }
            }
        }

        __syncthreads();               // all warps done reading this stage
        if (c + NSTAGE < NCH) issue(c + NSTAGE, c % NSTAGE);
    }

    // ---- epilogue: stage acc through smem for coalesced scatter ----
    float* sacc = (float*)(smem + SM_BUF);
    {
        const int r0 = aw + (lane >> 2);
        const int c0 = bw + 2 * (lane & 3);
#pragma unroll
        for (int fi = 0; fi < 2; fi++) {
#pragma unroll
            for (int j = 0; j < 4; j++) {
                int rr = r0 + fi * 16;
                int cc = c0 + j * 8;
                sacc[rr * ACCW + cc]           = acc[fi][j][0];
                sacc[rr * ACCW + cc + 1]       = acc[fi][j][1];
                sacc[(rr + 8) * ACCW + cc]     = acc[fi][j][2];
                sacc[(rr + 8) * ACCW + cc + 1] = acc[fi][j][3];
            }
        }
    }
    __syncthreads();

    {
        const int row = tid >> 2;
        const int q   = (tid & 3) * 32;
        if (m0 + row < cnt) {
            const int tok = stok[row];
            float* op = out + (size_t)tok * OUT_F + n0 + q;
            const float* sr = &sacc[row * ACCW + q];
#pragma unroll
            for (int i = 0; i < 8; i++) {
                float4 v = *(const float4*)(sr + i * 4);
                v.x += sbias[q + i * 4 + 0];
                v.y += sbias[q + i * 4 + 1];
                v.z += sbias[q + i * 4 + 2];
                v.w += sbias[q + i * 4 + 3];
                *(float4*)(op + i * 4) = v;
            }
        }
    }
}

// ---------------- launch ----------------
extern "C" void kernel_launch(void* const* d_in, const int* in_sizes, int n_in,
                              void* d_out, int out_size) {
    const float* x    = (const float*)d_in[0];
    const float* wght = (const float*)d_in[1];
    const float* bias = (const float*)d_in[2];
    const int*   eid  = (const int*)d_in[3];
    float* out = (float*)d_out;

    cudaFuncSetAttribute(k_gemm, cudaFuncAttributeMaxDynamicSharedMemorySize,
                         SMEM_TOTAL);

    __nv_bfloat16 *xh, *xl, *wh, *wl;
    cudaGetSymbolAddress((void**)&xh, g_xh);
    cudaGetSymbolAddress((void**)&xl, g_xl);
    cudaGetSymbolAddress((void**)&wh, g_wh);
    cudaGetSymbolAddress((void**)&wl, g_wl);

    k_zero<<<1, 64>>>();
    k_scatter<<<(NTOK + 255) / 256, 256>>>(eid, out);

    const int nx8 = NTOK * IN_F / 8;                 // 8388608
    const int nw8 = NUM_E * OUT_F * IN_F / 8;        // 2097152
    k_cvt<<<nx8 / 256, 256>>>(x, xh, xl, nx8);
    k_cvt<<<nw8 / 256, 256>>>(wght, wh, wl, nw8);

    dim3 grid((CAPACITY / TM) * (OUT_F / TN), NUM_E);
    k_gemm<<<grid, THREADS, SMEM_TOTAL>>>(bias, out);
}

// round 5
// speedup vs baseline: 2.6989x; 1.2998x over previous
#include <cuda_runtime.h>
#include <cuda_fp16.h>
#include <cstdint>

// ---------------- problem constants ----------------
#define NUM_E    64
#define IN_F     512
#define OUT_F    512
#define NTOK     131072
#define CAPACITY 3072

// ---------------- tiling ----------------
#define TM 128
#define TN 128
#define KC 64                  // K chunk (64 fp16 = 128B row)
#define NCH (IN_F / KC)        // 8
#define THREADS 512
#define NSTAGE 4

// ---------------- smem layout (bytes) ----------------
#define SM_TOK   0                       // 128 ints
#define SM_BIAS  512                     // 128 floats
#define SM_BUF   1024
#define TILE_SZ  (128 * 64 * 2)          // 16384 per tile
#define STG_SZ   (3 * TILE_SZ)           // 49152: XF, WH, WL
#define SMEM_TOTAL (SM_BUF + NSTAGE * STG_SZ)   // 197632

#define ACCW 132                          // padded epilogue stride (floats)

#define SWZ(off) ((off) ^ (((off) >> 3) & 0x70))

__device__ int g_cnt[NUM_E];
__device__ int g_perm[NUM_E * CAPACITY];

// preconverted operands: X single fp16; W split fp16 hi/lo
__device__ __half g_xf[(size_t)NTOK * IN_F];           // 128 MB
__device__ __half g_wh[(size_t)NUM_E * OUT_F * IN_F];  // 32 MB
__device__ __half g_wl[(size_t)NUM_E * OUT_F * IN_F];  // 32 MB

// ---------------- PTX helpers ----------------
__device__ __forceinline__ uint32_t smem_u32(const void* p) {
    uint32_t a;
    asm("{ .reg .u64 t; cvta.to.shared.u64 t, %1; cvt.u32.u64 %0, t; }"
        : "=r"(a) : "l"(p));
    return a;
}
__device__ __forceinline__ void cp16(uint32_t dst, const void* src) {
    asm volatile("cp.async.cg.shared.global [%0], [%1], 16;"
                 :: "r"(dst), "l"(src));
}
__device__ __forceinline__ void cp_commit() {
    asm volatile("cp.async.commit_group;" ::: "memory");
}
template <int N>
__device__ __forceinline__ void cp_wait() {
    asm volatile("cp.async.wait_group %0;" :: "n"(N) : "memory");
}
__device__ __forceinline__ void ldsm4(uint32_t* r, uint32_t a) {
    asm volatile("ldmatrix.sync.aligned.m8n8.x4.shared.b16 {%0,%1,%2,%3}, [%4];"
                 : "=r"(r[0]), "=r"(r[1]), "=r"(r[2]), "=r"(r[3]) : "r"(a));
}
__device__ __forceinline__ void mma16816(float* d, const uint32_t* a,
                                         const uint32_t* b) {
    asm volatile(
        "mma.sync.aligned.m16n8k16.row.col.f32.f16.f16.f32 "
        "{%0,%1,%2,%3}, {%4,%5,%6,%7}, {%8,%9}, {%0,%1,%2,%3};"
        : "+f"(d[0]), "+f"(d[1]), "+f"(d[2]), "+f"(d[3])
        : "r"(a[0]), "r"(a[1]), "r"(a[2]), "r"(a[3]), "r"(b[0]), "r"(b[1]));
}

// ---------------- routing ----------------
__global__ void k_zero() {
    if (threadIdx.x < NUM_E) g_cnt[threadIdx.x] = 0;
}

__global__ void k_scatter(const int* __restrict__ eid, float* __restrict__ out) {
    int t = blockIdx.x * blockDim.x + threadIdx.x;
    if (t >= NTOK) return;
    int e = eid[t];
    int r = atomicAdd(&g_cnt[e], 1);
    if (r < CAPACITY) {
        g_perm[e * CAPACITY + r] = t;
    } else {
        float4* o = (float4*)(out + (size_t)t * OUT_F);
        float4 z = make_float4(0.f, 0.f, 0.f, 0.f);
        #pragma unroll 4
        for (int i = 0; i < OUT_F / 4; i++) o[i] = z;
    }
}

// ---------------- pre-pass: x -> single fp16 ----------------
__global__ __launch_bounds__(256)
void k_cvt_x(const float* __restrict__ src, __half* __restrict__ dst, int n8) {
    int g = blockIdx.x * blockDim.x + threadIdx.x;
    if (g >= n8) return;
    const float4 v0 = *(const float4*)(src + (size_t)g * 8);
    const float4 v1 = *(const float4*)(src + (size_t)g * 8 + 4);
    float f[8] = {v0.x, v0.y, v0.z, v0.w, v1.x, v1.y, v1.z, v1.w};
    uint32_t H[4];
#pragma unroll
    for (int j = 0; j < 4; j++) {
        __half h0 = __float2half_rn(f[2 * j]);
        __half h1 = __float2half_rn(f[2 * j + 1]);
        H[j] = ((uint32_t)__half_as_ushort(h1) << 16) | __half_as_ushort(h0);
    }
    *(uint4*)(dst + (size_t)g * 8) = make_uint4(H[0], H[1], H[2], H[3]);
}

// ---------------- pre-pass: w -> fp16 hi/lo split ----------------
__global__ __launch_bounds__(256)
void k_cvt_w(const float* __restrict__ src, __half* __restrict__ hi,
             __half* __restrict__ lo, int n8) {
    int g = blockIdx.x * blockDim.x + threadIdx.x;
    if (g >= n8) return;
    const float4 v0 = *(const float4*)(src + (size_t)g * 8);
    const float4 v1 = *(const float4*)(src + (size_t)g * 8 + 4);
    float f[8] = {v0.x, v0.y, v0.z, v0.w, v1.x, v1.y, v1.z, v1.w};
    uint32_t H[4], L[4];
#pragma unroll
    for (int j = 0; j < 4; j++) {
        __half h0 = __float2half_rn(f[2 * j]);
        __half h1 = __float2half_rn(f[2 * j + 1]);
        __half l0 = __float2half_rn(f[2 * j]     - __half2float(h0));
        __half l1 = __float2half_rn(f[2 * j + 1] - __half2float(h1));
        H[j] = ((uint32_t)__half_as_ushort(h1) << 16) | __half_as_ushort(h0);
        L[j] = ((uint32_t)__half_as_ushort(l1) << 16) | __half_as_ushort(l0);
    }
    *(uint4*)(hi + (size_t)g * 8) = make_uint4(H[0], H[1], H[2], H[3]);
    *(uint4*)(lo + (size_t)g * 8) = make_uint4(L[0], L[1], L[2], L[3]);
}

// ---------------- main GEMM (2-product MMA mainloop) ----------------
__global__ __launch_bounds__(THREADS, 1)
void k_gemm(const float* __restrict__ bias, float* __restrict__ out) {
    extern __shared__ char smem[];

    const int e = blockIdx.y;
    int cnt = g_cnt[e];
    if (cnt > CAPACITY) cnt = CAPACITY;
    const int m0 = (blockIdx.x >> 2) * TM;
    if (m0 >= cnt) return;
    const int n0 = (blockIdx.x & 3) * TN;

    const int tid  = threadIdx.x;
    const int lane = tid & 31;
    const int wid  = tid >> 5;

    int*   stok  = (int*)(smem + SM_TOK);
    float* sbias = (float*)(smem + SM_BIAS);

    if (tid < TM) {
        stok[tid] = g_perm[e * CAPACITY + m0 + ((m0 + tid < cnt) ? tid : 0)];
    } else if (tid < 2 * TM) {
        sbias[tid - TM] = bias[e * OUT_F + n0 + (tid - TM)];
    }
    __syncthreads();

    const uint32_t sb = smem_u32(smem);
    const size_t wrow0 = ((size_t)e * OUT_F + n0) * IN_F;

    // cp.async: 3072 x 16B chunks per stage, 6 per thread
    // g = tid + i*512 : tile = g>>10 (0:XF 1:WH 2:WL), row=(g>>3)&127, kg=g&7
    auto issue = [&](int c, int st) {
        const uint32_t stg = sb + SM_BUF + st * STG_SZ;
        const int k0 = c * KC;
#pragma unroll
        for (int i = 0; i < 6; i++) {
            int g = tid + i * THREADS;
            int tile = g >> 10, row = (g >> 3) & 127, kg = g & 7;
            uint32_t dst = stg + tile * TILE_SZ + SWZ((uint32_t)(row * 128 + kg * 16));
            const __half* src;
            if (tile == 0) {
                src = g_xf + (size_t)stok[row] * IN_F + k0 + kg * 8;
            } else {
                const __half* base = (tile == 1) ? g_wh : g_wl;
                src = base + wrow0 + (size_t)row * IN_F + k0 + kg * 8;
            }
            cp16(dst, src);
        }
        cp_commit();
    };

    // per-warp ldmatrix address precompute (stage-relative)
    const int aw = (wid & 3) * 32;   // warp M offset
    const int bw = (wid >> 2) * 32;  // warp N offset

    uint32_t a_off[2], a_mask[2];
    {
        int ar = lane & 15;
#pragma unroll
        for (int fi = 0; fi < 2; fi++) {
            int r = aw + fi * 16 + ar;
            a_off[fi] = (uint32_t)(r * 128);
            a_mask[fi] = (r & 7) * 16;
        }
    }
    const uint32_t a_klane = (lane & 16) ? 16u : 0u;

    uint32_t b_off[2], b_mask[2];
    {
        int br = (lane & 7) + ((lane & 16) ? 8 : 0);
#pragma unroll
        for (int jp = 0; jp < 2; jp++) {
            int r = bw + jp * 16 + br;
            b_off[jp] = (uint32_t)(TILE_SZ + r * 128);   // WH tile base
            b_mask[jp] = (r & 7) * 16;
        }
    }
    const uint32_t b_klane = (lane & 8) ? 16u : 0u;

    float acc[2][4][4];
#pragma unroll
    for (int i = 0; i < 2; i++)
#pragma unroll
        for (int j = 0; j < 4; j++)
#pragma unroll
            for (int q = 0; q < 4; q++) acc[i][j][q] = 0.f;

    // ---- pipeline: 4 buffers, 3 chunks in flight ----
    issue(0, 0);
    issue(1, 1);
    issue(2, 2);

#pragma unroll
    for (int c = 0; c < NCH; c++) {
        if (c <= NCH - 3)      cp_wait<2>();
        else if (c == NCH - 2) cp_wait<1>();
        else                   cp_wait<0>();
        __syncthreads();   // stage c fully visible to all warps

        // issue into stage (c+3)%4 = (c-1)%4; safe: all warps are past
        // the barrier above, so chunk c-1's reads of that stage are done.
        if (c + 3 < NCH) issue(c + 3, (c + 3) % NSTAGE);

        const uint32_t stg = sb + SM_BUF + (c % NSTAGE) * STG_SZ;

#pragma unroll
        for (int s = 0; s < 4; s++) {
            uint32_t xf[2][4], wh[2][4], wl[2][4];
            const uint32_t kcol = (uint32_t)(s * 32);
#pragma unroll
            for (int fi = 0; fi < 2; fi++) {
                uint32_t ad = stg + a_off[fi] + ((kcol + a_klane) ^ a_mask[fi]);
                ldsm4(xf[fi], ad);
            }
#pragma unroll
            for (int jp = 0; jp < 2; jp++) {
                uint32_t bd = stg + b_off[jp] + ((kcol + b_klane) ^ b_mask[jp]);
                ldsm4(wh[jp], bd);
                ldsm4(wl[jp], bd + TILE_SZ);
            }
#pragma unroll
            for (int fi = 0; fi < 2; fi++) {
#pragma unroll
                for (int j = 0; j < 4; j++) {
                    const uint32_t* Bh = &wh[j >> 1][(j & 1) * 2];
                    const uint32_t* Bl = &wl[j >> 1][(j & 1) * 2];
                    mma16816(acc[fi][j], xf[fi], Bh);
                    mma16816(acc[fi][j], xf[fi], Bl);
                }
            }
        }
    }

    // ---- epilogue: stage acc through smem for coalesced scatter ----
    __syncthreads();
    float* sacc = (float*)(smem + SM_BUF);
    {
        const int r0 = aw + (lane >> 2);
        const int c0 = bw + 2 * (lane & 3);
#pragma unroll
        for (int fi = 0; fi < 2; fi++) {
#pragma unroll
            for (int j = 0; j < 4; j++) {
                int rr = r0 + fi * 16;
                int cc = c0 + j * 8;
                sacc[rr * ACCW + cc]           = acc[fi][j][0];
                sacc[rr * ACCW + cc + 1]       = acc[fi][j][1];
                sacc[(rr + 8) * ACCW + cc]     = acc[fi][j][2];
                sacc[(rr + 8) * ACCW + cc + 1] = acc[fi][j][3];
            }
        }
    }
    __syncthreads();

    {
        const int row = tid >> 2;
        const int q   = (tid & 3) * 32;
        if (m0 + row < cnt) {
            const int tok = stok[row];
            float* op = out + (size_t)tok * OUT_F + n0 + q;
            const float* sr = &sacc[row * ACCW + q];
#pragma unroll
            for (int i = 0; i < 8; i++) {
                float4 v = *(const float4*)(sr + i * 4);
                v.x += sbias[q + i * 4 + 0];
                v.y += sbias[q + i * 4 + 1];
                v.z += sbias[q + i * 4 + 2];
                v.w += sbias[q + i * 4 + 3];
                *(float4*)(op + i * 4) = v;
            }
        }
    }
}

// ---------------- launch ----------------
extern "C" void kernel_launch(void* const* d_in, const int* in_sizes, int n_in,
                              void* d_out, int out_size) {
    const float* x    = (const float*)d_in[0];
    const float* wght = (const float*)d_in[1];
    const float* bias = (const float*)d_in[2];
    const int*   eid  = (const int*)d_in[3];
    float* out = (float*)d_out;

    cudaFuncSetAttribute(k_gemm, cudaFuncAttributeMaxDynamicSharedMemorySize,
                         SMEM_TOTAL);

    __half *xf, *wh, *wl;
    cudaGetSymbolAddress((void**)&xf, g_xf);
    cudaGetSymbolAddress((void**)&wh, g_wh);
    cudaGetSymbolAddress((void**)&wl, g_wl);

    k_zero<<<1, 64>>>();
    k_scatter<<<(NTOK + 255) / 256, 256>>>(eid, out);

    const int nx8 = NTOK * IN_F / 8;                 // 8388608
    const int nw8 = NUM_E * OUT_F * IN_F / 8;        // 2097152
    k_cvt_x<<<nx8 / 256, 256>>>(x, xf, nx8);
    k_cvt_w<<<nw8 / 256, 256>>>(wght, wh, wl, nw8);

    dim3 grid((CAPACITY / TM) * (OUT_F / TN), NUM_E);
    k_gemm<<<grid, THREADS, SMEM_TOTAL>>>(bias, out);
}

// round 6
// speedup vs baseline: 3.3058x; 1.2249x over previous
#include <cuda_runtime.h>
#include <cuda_fp16.h>
#include <cstdint>

// ---------------- problem constants ----------------
#define NUM_E    64
#define IN_F     512
#define OUT_F    512
#define NTOK     131072
#define CAPACITY 3072

// ---------------- tiling ----------------
#define TM 128
#define TN 128
#define KC 64                  // K chunk (64 fp16 = 128B row)
#define NCH (IN_F / KC)        // 8
#define THREADS 512
#define NSTAGE 4

// ---------------- smem layout (bytes) ----------------
#define SM_TOK   0                       // 128 ints
#define SM_BIAS  512                     // 128 floats
#define SM_BUF   1024
#define TILE_SZ  (128 * 64 * 2)          // 16384 per tile
#define STG_SZ   (2 * TILE_SZ)           // 32768: XF, WF
#define SMEM_TOTAL (SM_BUF + NSTAGE * STG_SZ)   // 132096

#define ACCW 132                          // padded epilogue stride (floats)

#define SWZ(off) ((off) ^ (((off) >> 3) & 0x70))

__device__ int g_cnt[NUM_E];
__device__ int g_perm[NUM_E * CAPACITY];

// preconverted fp16 operands
__device__ __half g_xf[(size_t)NTOK * IN_F];           // 128 MB
__device__ __half g_wf[(size_t)NUM_E * OUT_F * IN_F];  // 32 MB

// ---------------- PTX helpers ----------------
__device__ __forceinline__ uint32_t smem_u32(const void* p) {
    uint32_t a;
    asm("{ .reg .u64 t; cvta.to.shared.u64 t, %1; cvt.u32.u64 %0, t; }"
        : "=r"(a) : "l"(p));
    return a;
}
__device__ __forceinline__ void cp16(uint32_t dst, const void* src) {
    asm volatile("cp.async.cg.shared.global [%0], [%1], 16;"
                 :: "r"(dst), "l"(src));
}
__device__ __forceinline__ void cp_commit() {
    asm volatile("cp.async.commit_group;" ::: "memory");
}
template <int N>
__device__ __forceinline__ void cp_wait() {
    asm volatile("cp.async.wait_group %0;" :: "n"(N) : "memory");
}
__device__ __forceinline__ void ldsm4(uint32_t* r, uint32_t a) {
    asm volatile("ldmatrix.sync.aligned.m8n8.x4.shared.b16 {%0,%1,%2,%3}, [%4];"
                 : "=r"(r[0]), "=r"(r[1]), "=r"(r[2]), "=r"(r[3]) : "r"(a));
}
__device__ __forceinline__ void mma16816(float* d, const uint32_t* a,
                                         const uint32_t* b) {
    asm volatile(
        "mma.sync.aligned.m16n8k16.row.col.f32.f16.f16.f32 "
        "{%0,%1,%2,%3}, {%4,%5,%6,%7}, {%8,%9}, {%0,%1,%2,%3};"
        : "+f"(d[0]), "+f"(d[1]), "+f"(d[2]), "+f"(d[3])
        : "r"(a[0]), "r"(a[1]), "r"(a[2]), "r"(a[3]), "r"(b[0]), "r"(b[1]));
}

// ---------------- routing ----------------
__global__ void k_zero() {
    if (threadIdx.x < NUM_E) g_cnt[threadIdx.x] = 0;
}

__global__ void k_scatter(const int* __restrict__ eid, float* __restrict__ out) {
    int t = blockIdx.x * blockDim.x + threadIdx.x;
    if (t >= NTOK) return;
    int e = eid[t];
    int r = atomicAdd(&g_cnt[e], 1);
    if (r < CAPACITY) {
        g_perm[e * CAPACITY + r] = t;
    } else {
        float4* o = (float4*)(out + (size_t)t * OUT_F);
        float4 z = make_float4(0.f, 0.f, 0.f, 0.f);
        #pragma unroll 4
        for (int i = 0; i < OUT_F / 4; i++) o[i] = z;
    }
}

// ---------------- pre-pass: fp32 -> fp16 ----------------
__global__ __launch_bounds__(256)
void k_cvt(const float* __restrict__ src, __half* __restrict__ dst, int n8) {
    int g = blockIdx.x * blockDim.x + threadIdx.x;
    if (g >= n8) return;
    const float4 v0 = *(const float4*)(src + (size_t)g * 8);
    const float4 v1 = *(const float4*)(src + (size_t)g * 8 + 4);
    float f[8] = {v0.x, v0.y, v0.z, v0.w, v1.x, v1.y, v1.z, v1.w};
    uint32_t H[4];
#pragma unroll
    for (int j = 0; j < 4; j++) {
        __half h0 = __float2half_rn(f[2 * j]);
        __half h1 = __float2half_rn(f[2 * j + 1]);
        H[j] = ((uint32_t)__half_as_ushort(h1) << 16) | __half_as_ushort(h0);
    }
    *(uint4*)(dst + (size_t)g * 8) = make_uint4(H[0], H[1], H[2], H[3]);
}

// ---------------- main GEMM (single-product MMA mainloop) ----------------
__global__ __launch_bounds__(THREADS, 1)
void k_gemm(const float* __restrict__ bias, float* __restrict__ out) {
    extern __shared__ char smem[];

    const int e = blockIdx.y;
    int cnt = g_cnt[e];
    if (cnt > CAPACITY) cnt = CAPACITY;
    const int m0 = (blockIdx.x >> 2) * TM;
    if (m0 >= cnt) return;
    const int n0 = (blockIdx.x & 3) * TN;

    const int tid  = threadIdx.x;
    const int lane = tid & 31;
    const int wid  = tid >> 5;

    int*   stok  = (int*)(smem + SM_TOK);
    float* sbias = (float*)(smem + SM_BIAS);

    if (tid < TM) {
        stok[tid] = g_perm[e * CAPACITY + m0 + ((m0 + tid < cnt) ? tid : 0)];
    } else if (tid < 2 * TM) {
        sbias[tid - TM] = bias[e * OUT_F + n0 + (tid - TM)];
    }
    __syncthreads();

    const uint32_t sb = smem_u32(smem);
    const size_t wrow0 = ((size_t)e * OUT_F + n0) * IN_F;

    // cp.async: 2048 x 16B chunks per stage, 4 per thread
    // g = tid + i*512 : tile = g>>10 (0:XF 1:WF), row=(g>>3)&127, kg=g&7
    auto issue = [&](int c, int st) {
        const uint32_t stg = sb + SM_BUF + st * STG_SZ;
        const int k0 = c * KC;
#pragma unroll
        for (int i = 0; i < 4; i++) {
            int g = tid + i * THREADS;
            int tile = g >> 10, row = (g >> 3) & 127, kg = g & 7;
            uint32_t dst = stg + tile * TILE_SZ + SWZ((uint32_t)(row * 128 + kg * 16));
            const __half* src;
            if (tile == 0) {
                src = g_xf + (size_t)stok[row] * IN_F + k0 + kg * 8;
            } else {
                src = g_wf + wrow0 + (size_t)row * IN_F + k0 + kg * 8;
            }
            cp16(dst, src);
        }
        cp_commit();
    };

    // per-warp ldmatrix address precompute (stage-relative)
    const int aw = (wid & 3) * 32;   // warp M offset
    const int bw = (wid >> 2) * 32;  // warp N offset

    uint32_t a_off[2], a_mask[2];
    {
        int ar = lane & 15;
#pragma unroll
        for (int fi = 0; fi < 2; fi++) {
            int r = aw + fi * 16 + ar;
            a_off[fi] = (uint32_t)(r * 128);
            a_mask[fi] = (r & 7) * 16;
        }
    }
    const uint32_t a_klane = (lane & 16) ? 16u : 0u;

    uint32_t b_off[2], b_mask[2];
    {
        int br = (lane & 7) + ((lane & 16) ? 8 : 0);
#pragma unroll
        for (int jp = 0; jp < 2; jp++) {
            int r = bw + jp * 16 + br;
            b_off[jp] = (uint32_t)(TILE_SZ + r * 128);   // WF tile base
            b_mask[jp] = (r & 7) * 16;
        }
    }
    const uint32_t b_klane = (lane & 8) ? 16u : 0u;

    float acc[2][4][4];
#pragma unroll
    for (int i = 0; i < 2; i++)
#pragma unroll
        for (int j = 0; j < 4; j++)
#pragma unroll
            for (int q = 0; q < 4; q++) acc[i][j][q] = 0.f;

    // ---- pipeline: 4 buffers, 3 chunks in flight ----
    issue(0, 0);
    issue(1, 1);
    issue(2, 2);

#pragma unroll
    for (int c = 0; c < NCH; c++) {
        if (c <= NCH - 3)      cp_wait<2>();
        else if (c == NCH - 2) cp_wait<1>();
        else                   cp_wait<0>();
        __syncthreads();   // stage c fully visible to all warps

        // issue into stage (c+3)%4; all warps have passed the barrier, so
        // chunk c-1's reads of that buffer are complete.
        if (c + 3 < NCH) issue(c + 3, (c + 3) % NSTAGE);

        const uint32_t stg = sb + SM_BUF + (c % NSTAGE) * STG_SZ;

#pragma unroll
        for (int s = 0; s < 4; s++) {
            uint32_t xf[2][4], wf[2][4];
            const uint32_t kcol = (uint32_t)(s * 32);
#pragma unroll
            for (int fi = 0; fi < 2; fi++) {
                uint32_t ad = stg + a_off[fi] + ((kcol + a_klane) ^ a_mask[fi]);
                ldsm4(xf[fi], ad);
            }
#pragma unroll
            for (int jp = 0; jp < 2; jp++) {
                uint32_t bd = stg + b_off[jp] + ((kcol + b_klane) ^ b_mask[jp]);
                ldsm4(wf[jp], bd);
            }
#pragma unroll
            for (int fi = 0; fi < 2; fi++) {
#pragma unroll
                for (int j = 0; j < 4; j++) {
                    mma16816(acc[fi][j], xf[fi], &wf[j >> 1][(j & 1) * 2]);
                }
            }
        }
    }

    // ---- epilogue: stage acc through smem for coalesced scatter ----
    __syncthreads();
    float* sacc = (float*)(smem + SM_BUF);
    {
        const int r0 = aw + (lane >> 2);
        const int c0 = bw + 2 * (lane & 3);
#pragma unroll
        for (int fi = 0; fi < 2; fi++) {
#pragma unroll
            for (int j = 0; j < 4; j++) {
                int rr = r0 + fi * 16;
                int cc = c0 + j * 8;
                sacc[rr * ACCW + cc]           = acc[fi][j][0];
                sacc[rr * ACCW + cc + 1]       = acc[fi][j][1];
                sacc[(rr + 8) * ACCW + cc]     = acc[fi][j][2];
                sacc[(rr + 8) * ACCW + cc + 1] = acc[fi][j][3];
            }
        }
    }
    __syncthreads();

    {
        const int row = tid >> 2;
        const int q   = (tid & 3) * 32;
        if (m0 + row < cnt) {
            const int tok = stok[row];
            float* op = out + (size_t)tok * OUT_F + n0 + q;
            const float* sr = &sacc[row * ACCW + q];
#pragma unroll
            for (int i = 0; i < 8; i++) {
                float4 v = *(const float4*)(sr + i * 4);
                v.x += sbias[q + i * 4 + 0];
                v.y += sbias[q + i * 4 + 1];
                v.z += sbias[q + i * 4 + 2];
                v.w += sbias[q + i * 4 + 3];
                *(float4*)(op + i * 4) = v;
            }
        }
    }
}

// ---------------- launch ----------------
extern "C" void kernel_launch(void* const* d_in, const int* in_sizes, int n_in,
                              void* d_out, int out_size) {
    const float* x    = (const float*)d_in[0];
    const float* wght = (const float*)d_in[1];
    const float* bias = (const float*)d_in[2];
    const int*   eid  = (const int*)d_in[3];
    float* out = (float*)d_out;

    cudaFuncSetAttribute(k_gemm, cudaFuncAttributeMaxDynamicSharedMemorySize,
                         SMEM_TOTAL);

    __half *xf, *wf;
    cudaGetSymbolAddress((void**)&xf, g_xf);
    cudaGetSymbolAddress((void**)&wf, g_wf);

    k_zero<<<1, 64>>>();
    k_scatter<<<(NTOK + 255) / 256, 256>>>(eid, out);

    const int nx8 = NTOK * IN_F / 8;                 // 8388608
    const int nw8 = NUM_E * OUT_F * IN_F / 8;        // 2097152
    k_cvt<<<nx8 / 256, 256>>>(x, xf, nx8);
    k_cvt<<<nw8 / 256, 256>>>(wght, wf, nw8);

    dim3 grid((CAPACITY / TM) * (OUT_F / TN), NUM_E);
    k_gemm<<<grid, THREADS, SMEM_TOTAL>>>(bias, out);
}

// round 7
// speedup vs baseline: 3.8484x; 1.1641x over previous
#include <cuda_runtime.h>
#include <cuda_fp16.h>
#include <cstdint>

// ---------------- problem constants ----------------
#define NUM_E    64
#define IN_F     512
#define OUT_F    512
#define NTOK     131072
#define CAPACITY 3072

// ---------------- tiling ----------------
#define TM 128
#define TN 64
#define KC 64                  // K chunk (64 fp16 = 128B row)
#define NCH (IN_F / KC)        // 8
#define THREADS 256
#define NSTAGE 4
#define NTILES (OUT_F / TN)    // 8
#define MTILES (CAPACITY / TM) // 24

// ---------------- smem layout (bytes) ----------------
#define SM_TOK   0                       // 128 ints
#define SM_BIAS  512                     // 64 floats
#define SM_BUF   1024
#define TILE_X   (TM * KC * 2)           // 16384
#define TILE_W   (TN * KC * 2)           // 8192
#define STG_SZ   (TILE_X + TILE_W)       // 24576
#define SMEM_TOTAL (SM_BUF + NSTAGE * STG_SZ)   // 99328

#define ACCW 68                           // padded epilogue stride (floats)

#define SWZ(off) ((off) ^ (((off) >> 3) & 0x70))

__device__ int g_cnt[NUM_E];
__device__ int g_perm[NUM_E * CAPACITY];

// preconverted fp16 operands
__device__ __half g_xf[(size_t)NTOK * IN_F];           // 128 MB
__device__ __half g_wf[(size_t)NUM_E * OUT_F * IN_F];  // 32 MB

// ---------------- PTX helpers ----------------
__device__ __forceinline__ uint32_t smem_u32(const void* p) {
    uint32_t a;
    asm("{ .reg .u64 t; cvta.to.shared.u64 t, %1; cvt.u32.u64 %0, t; }"
        : "=r"(a) : "l"(p));
    return a;
}
__device__ __forceinline__ void cp16(uint32_t dst, const void* src) {
    asm volatile("cp.async.cg.shared.global [%0], [%1], 16;"
                 :: "r"(dst), "l"(src));
}
__device__ __forceinline__ void cp_commit() {
    asm volatile("cp.async.commit_group;" ::: "memory");
}
template <int N>
__device__ __forceinline__ void cp_wait() {
    asm volatile("cp.async.wait_group %0;" :: "n"(N) : "memory");
}
__device__ __forceinline__ void ldsm4(uint32_t* r, uint32_t a) {
    asm volatile("ldmatrix.sync.aligned.m8n8.x4.shared.b16 {%0,%1,%2,%3}, [%4];"
                 : "=r"(r[0]), "=r"(r[1]), "=r"(r[2]), "=r"(r[3]) : "r"(a));
}
__device__ __forceinline__ void mma16816(float* d, const uint32_t* a,
                                         const uint32_t* b) {
    asm volatile(
        "mma.sync.aligned.m16n8k16.row.col.f32.f16.f16.f32 "
        "{%0,%1,%2,%3}, {%4,%5,%6,%7}, {%8,%9}, {%0,%1,%2,%3};"
        : "+f"(d[0]), "+f"(d[1]), "+f"(d[2]), "+f"(d[3])
        : "r"(a[0]), "r"(a[1]), "r"(a[2]), "r"(a[3]), "r"(b[0]), "r"(b[1]));
}

// ---------------- routing ----------------
__global__ void k_zero() {
    if (threadIdx.x < NUM_E) g_cnt[threadIdx.x] = 0;
}

__global__ void k_scatter(const int* __restrict__ eid, float* __restrict__ out) {
    int t = blockIdx.x * blockDim.x + threadIdx.x;
    if (t >= NTOK) return;
    int e = eid[t];
    int r = atomicAdd(&g_cnt[e], 1);
    if (r < CAPACITY) {
        g_perm[e * CAPACITY + r] = t;
    } else {
        float4* o = (float4*)(out + (size_t)t * OUT_F);
        float4 z = make_float4(0.f, 0.f, 0.f, 0.f);
        #pragma unroll 4
        for (int i = 0; i < OUT_F / 4; i++) o[i] = z;
    }
}

// ---------------- pre-pass: fp32 -> fp16, 16 elems/thread (MLP 4) ----------------
__global__ __launch_bounds__(256)
void k_cvt(const float* __restrict__ src, __half* __restrict__ dst, int n16) {
    int g = blockIdx.x * blockDim.x + threadIdx.x;
    if (g >= n16) return;
    const float4* s = (const float4*)(src + (size_t)g * 16);
    float4 v0 = s[0], v1 = s[1], v2 = s[2], v3 = s[3];
    float f[16] = {v0.x, v0.y, v0.z, v0.w, v1.x, v1.y, v1.z, v1.w,
                   v2.x, v2.y, v2.z, v2.w, v3.x, v3.y, v3.z, v3.w};
    uint32_t H[8];
#pragma unroll
    for (int j = 0; j < 8; j++) {
        __half h0 = __float2half_rn(f[2 * j]);
        __half h1 = __float2half_rn(f[2 * j + 1]);
        H[j] = ((uint32_t)__half_as_ushort(h1) << 16) | __half_as_ushort(h0);
    }
    uint4* d = (uint4*)(dst + (size_t)g * 16);
    d[0] = make_uint4(H[0], H[1], H[2], H[3]);
    d[1] = make_uint4(H[4], H[5], H[6], H[7]);
}

// ---------------- main GEMM: 128x64 tile, 256 threads, 2 CTAs/SM ----------------
__global__ __launch_bounds__(THREADS, 2)
void k_gemm(const float* __restrict__ bias, float* __restrict__ out) {
    extern __shared__ char smem[];

    const int e = blockIdx.y;
    int cnt = g_cnt[e];
    if (cnt > CAPACITY) cnt = CAPACITY;
    const int m0 = (blockIdx.x >> 3) * TM;
    if (m0 >= cnt) return;
    const int n0 = (blockIdx.x & 7) * TN;

    const int tid  = threadIdx.x;
    const int lane = tid & 31;
    const int wid  = tid >> 5;

    int*   stok  = (int*)(smem + SM_TOK);
    float* sbias = (float*)(smem + SM_BIAS);

    if (tid < TM) {
        stok[tid] = g_perm[e * CAPACITY + m0 + ((m0 + tid < cnt) ? tid : 0)];
    } else if (tid < TM + TN) {
        sbias[tid - TM] = bias[e * OUT_F + n0 + (tid - TM)];
    }
    __syncthreads();

    const uint32_t sb = smem_u32(smem);
    const size_t wrow0 = ((size_t)e * OUT_F + n0) * IN_F;

    // cp.async: 1536 x 16B chunks per stage (X 1024 + W 512), 6 per thread
    auto issue = [&](int c, int st) {
        const uint32_t stg = sb + SM_BUF + st * STG_SZ;
        const int k0 = c * KC;
#pragma unroll
        for (int i = 0; i < 6; i++) {
            int g = tid + i * THREADS;              // 0..1535
            if (g < 1024) {
                int row = g >> 3, kg = g & 7;
                uint32_t dst = stg + SWZ((uint32_t)(row * 128 + kg * 16));
                cp16(dst, g_xf + (size_t)stok[row] * IN_F + k0 + kg * 8);
            } else {
                int gw = g - 1024;
                int row = gw >> 3, kg = gw & 7;
                uint32_t dst = stg + TILE_X + SWZ((uint32_t)(row * 128 + kg * 16));
                cp16(dst, g_wf + wrow0 + (size_t)row * IN_F + k0 + kg * 8);
            }
        }
        cp_commit();
    };

    // per-warp ldmatrix address precompute (stage-relative)
    const int aw = (wid & 3) * 32;   // warp M offset (4 warps)
    const int bw = (wid >> 2) * 32;  // warp N offset (2 groups)

    uint32_t a_off[2], a_mask[2];
    {
        int ar = lane & 15;
#pragma unroll
        for (int fi = 0; fi < 2; fi++) {
            int r = aw + fi * 16 + ar;
            a_off[fi] = (uint32_t)(r * 128);
            a_mask[fi] = (r & 7) * 16;
        }
    }
    const uint32_t a_klane = (lane & 16) ? 16u : 0u;

    uint32_t b_off[2], b_mask[2];
    {
        int br = (lane & 7) + ((lane & 16) ? 8 : 0);
#pragma unroll
        for (int jp = 0; jp < 2; jp++) {
            int r = bw + jp * 16 + br;
            b_off[jp] = (uint32_t)(TILE_X + r * 128);
            b_mask[jp] = (r & 7) * 16;
        }
    }
    const uint32_t b_klane = (lane & 8) ? 16u : 0u;

    float acc[2][4][4];
#pragma unroll
    for (int i = 0; i < 2; i++)
#pragma unroll
        for (int j = 0; j < 4; j++)
#pragma unroll
            for (int q = 0; q < 4; q++) acc[i][j][q] = 0.f;

    // ---- pipeline: 4 buffers, 3 chunks in flight ----
    issue(0, 0);
    issue(1, 1);
    issue(2, 2);

#pragma unroll
    for (int c = 0; c < NCH; c++) {
        if (c <= NCH - 3)      cp_wait<2>();
        else if (c == NCH - 2) cp_wait<1>();
        else                   cp_wait<0>();
        __syncthreads();   // stage c fully visible to all warps

        if (c + 3 < NCH) issue(c + 3, (c + 3) % NSTAGE);

        const uint32_t stg = sb + SM_BUF + (c % NSTAGE) * STG_SZ;

#pragma unroll
        for (int s = 0; s < 4; s++) {
            uint32_t xf[2][4], wf[2][4];
            const uint32_t kcol = (uint32_t)(s * 32);
#pragma unroll
            for (int fi = 0; fi < 2; fi++) {
                uint32_t ad = stg + a_off[fi] + ((kcol + a_klane) ^ a_mask[fi]);
                ldsm4(xf[fi], ad);
            }
#pragma unroll
            for (int jp = 0; jp < 2; jp++) {
                uint32_t bd = stg + b_off[jp] + ((kcol + b_klane) ^ b_mask[jp]);
                ldsm4(wf[jp], bd);
            }
#pragma unroll
            for (int fi = 0; fi < 2; fi++) {
#pragma unroll
                for (int j = 0; j < 4; j++) {
                    mma16816(acc[fi][j], xf[fi], &wf[j >> 1][(j & 1) * 2]);
                }
            }
        }
    }

    // ---- epilogue: stage acc through smem for coalesced scatter ----
    __syncthreads();
    float* sacc = (float*)(smem + SM_BUF);
    {
        const int r0 = aw + (lane >> 2);
        const int c0 = bw + 2 * (lane & 3);
#pragma unroll
        for (int fi = 0; fi < 2; fi++) {
#pragma unroll
            for (int j = 0; j < 4; j++) {
                int rr = r0 + fi * 16;
                int cc = c0 + j * 8;
                sacc[rr * ACCW + cc]           = acc[fi][j][0];
                sacc[rr * ACCW + cc + 1]       = acc[fi][j][1];
                sacc[(rr + 8) * ACCW + cc]     = acc[fi][j][2];
                sacc[(rr + 8) * ACCW + cc + 1] = acc[fi][j][3];
            }
        }
    }
    __syncthreads();

    {
        const int row = tid >> 1;                 // 0..127
        const int q   = (tid & 1) * 32;           // half of 64 cols
        if (m0 + row < cnt) {
            const int tok = stok[row];
            float* op = out + (size_t)tok * OUT_F + n0 + q;
            const float* sr = &sacc[row * ACCW + q];
#pragma unroll
            for (int i = 0; i < 8; i++) {
                float4 v = *(const float4*)(sr + i * 4);
                v.x += sbias[q + i * 4 + 0];
                v.y += sbias[q + i * 4 + 1];
                v.z += sbias[q + i * 4 + 2];
                v.w += sbias[q + i * 4 + 3];
                *(float4*)(op + i * 4) = v;
            }
        }
    }
}

// ---------------- launch ----------------
extern "C" void kernel_launch(void* const* d_in, const int* in_sizes, int n_in,
                              void* d_out, int out_size) {
    const float* x    = (const float*)d_in[0];
    const float* wght = (const float*)d_in[1];
    const float* bias = (const float*)d_in[2];
    const int*   eid  = (const int*)d_in[3];
    float* out = (float*)d_out;

    cudaFuncSetAttribute(k_gemm, cudaFuncAttributeMaxDynamicSharedMemorySize,
                         SMEM_TOTAL);

    __half *xf, *wf;
    cudaGetSymbolAddress((void**)&xf, g_xf);
    cudaGetSymbolAddress((void**)&wf, g_wf);

    k_zero<<<1, 64>>>();
    k_scatter<<<(NTOK + 255) / 256, 256>>>(eid, out);

    const int nx16 = NTOK * IN_F / 16;               // 4194304
    const int nw16 = NUM_E * OUT_F * IN_F / 16;      // 1048576
    k_cvt<<<nx16 / 256, 256>>>(x, xf, nx16);
    k_cvt<<<nw16 / 256, 256>>>(wght, wf, nw16);

    dim3 grid(MTILES * NTILES, NUM_E);
    k_gemm<<<grid, THREADS, SMEM_TOTAL>>>(bias, out);
}

// round 8
// speedup vs baseline: 4.3976x; 1.1427x over previous
#include <cuda_runtime.h>
#include <cuda_fp16.h>
#include <cstdint>

// ---------------- problem constants ----------------
#define NUM_E    64
#define IN_F     512
#define OUT_F    512
#define NTOK     131072
#define CAPACITY 3072

// ---------------- tiling ----------------
#define TM 128
#define TN 64
#define KC 64                  // K chunk (64 fp16 = 128B row)
#define NCH (IN_F / KC)        // 8
#define THREADS 256
#define NSTAGE 4
#define NTILES (OUT_F / TN)    // 8
#define MTILES (CAPACITY / TM) // 24

// ---------------- smem layout (bytes) ----------------
#define SM_TOK   0                       // 128 ints
#define SM_BIAS  512                     // 64 floats
#define SM_BUF   1024
#define TILE_X   (TM * KC * 2)           // 16384
#define TILE_W   (TN * KC * 2)           // 8192
#define STG_SZ   (TILE_X + TILE_W)       // 24576
#define SMEM_TOTAL (SM_BUF + NSTAGE * STG_SZ)   // 99328

#define ACCW 68                           // padded epilogue stride (floats)

#define SWZ(off) ((off) ^ (((off) >> 3) & 0x70))

__device__ int g_cnt[NUM_E];
__device__ int g_tok[NUM_E * CAPACITY];   // slot -> token id

// fp16 operands: xg permuted by expert slot; wf expert-major
__device__ __half g_xg[(size_t)NUM_E * CAPACITY * IN_F]; // 192 MB
__device__ __half g_wf[(size_t)NUM_E * OUT_F * IN_F];    // 32 MB

// ---------------- PTX helpers ----------------
__device__ __forceinline__ uint32_t smem_u32(const void* p) {
    uint32_t a;
    asm("{ .reg .u64 t; cvta.to.shared.u64 t, %1; cvt.u32.u64 %0, t; }"
        : "=r"(a) : "l"(p));
    return a;
}
__device__ __forceinline__ void cp16(uint32_t dst, const void* src) {
    asm volatile("cp.async.cg.shared.global [%0], [%1], 16;"
                 :: "r"(dst), "l"(src));
}
__device__ __forceinline__ void cp_commit() {
    asm volatile("cp.async.commit_group;" ::: "memory");
}
template <int N>
__device__ __forceinline__ void cp_wait() {
    asm volatile("cp.async.wait_group %0;" :: "n"(N) : "memory");
}
__device__ __forceinline__ void ldsm4(uint32_t* r, uint32_t a) {
    asm volatile("ldmatrix.sync.aligned.m8n8.x4.shared.b16 {%0,%1,%2,%3}, [%4];"
                 : "=r"(r[0]), "=r"(r[1]), "=r"(r[2]), "=r"(r[3]) : "r"(a));
}
__device__ __forceinline__ void mma16816(float* d, const uint32_t* a,
                                         const uint32_t* b) {
    asm volatile(
        "mma.sync.aligned.m16n8k16.row.col.f32.f16.f16.f32 "
        "{%0,%1,%2,%3}, {%4,%5,%6,%7}, {%8,%9}, {%0,%1,%2,%3};"
        : "+f"(d[0]), "+f"(d[1]), "+f"(d[2]), "+f"(d[3])
        : "r"(a[0]), "r"(a[1]), "r"(a[2]), "r"(a[3]), "r"(b[0]), "r"(b[1]));
}

// ---------------- zero counters ----------------
__global__ void k_zero() {
    if (threadIdx.x < NUM_E) g_cnt[threadIdx.x] = 0;
}

// ---------------- fused route + x->fp16 permuted write ----------------
// 256 tokens per block. Block-aggregated expert ranking, then each warp
// converts 32 token rows fp32->fp16 into xg[e*CAP + r].
#define RBLK 256
__global__ __launch_bounds__(RBLK)
void k_route(const float* __restrict__ x, const int* __restrict__ eid,
             float* __restrict__ out) {
    __shared__ int s_eid[RBLK];
    __shared__ int s_slot[RBLK];
    __shared__ int s_hist[NUM_E];
    __shared__ int s_base[NUM_E];
    __shared__ int s_cur[NUM_E];

    const int tid = threadIdx.x;
    const int t0  = blockIdx.x * RBLK;

    int e = eid[t0 + tid];
    s_eid[tid] = e;
    if (tid < NUM_E) { s_hist[tid] = 0; s_cur[tid] = 0; }
    __syncthreads();
    atomicAdd(&s_hist[e], 1);
    __syncthreads();
    if (tid < NUM_E) {
        int h = s_hist[tid];
        s_base[tid] = h ? atomicAdd(&g_cnt[tid], h) : 0;
    }
    __syncthreads();
    {
        int r = s_base[e] + atomicAdd(&s_cur[e], 1);
        if (r < CAPACITY) {
            int slot = e * CAPACITY + r;
            g_tok[slot] = t0 + tid;
            s_slot[tid] = slot;
        } else {
            s_slot[tid] = -1;
        }
    }
    __syncthreads();

    // conversion: warp w handles rows [w*32, w*32+32)
    const int lane = tid & 31;
    const int wrp  = tid >> 5;
#pragma unroll 4
    for (int i = 0; i < 32; i++) {
        const int row = wrp * 32 + i;
        const int slot = s_slot[row];
        const float* src = x + (size_t)(t0 + row) * IN_F + lane * 16;
        if (slot >= 0) {
            float4 v0 = *(const float4*)(src + 0);
            float4 v1 = *(const float4*)(src + 4);
            float4 v2 = *(const float4*)(src + 8);
            float4 v3 = *(const float4*)(src + 12);
            float f[16] = {v0.x, v0.y, v0.z, v0.w, v1.x, v1.y, v1.z, v1.w,
                           v2.x, v2.y, v2.z, v2.w, v3.x, v3.y, v3.z, v3.w};
            uint32_t H[8];
#pragma unroll
            for (int j = 0; j < 8; j++) {
                __half h0 = __float2half_rn(f[2 * j]);
                __half h1 = __float2half_rn(f[2 * j + 1]);
                H[j] = ((uint32_t)__half_as_ushort(h1) << 16) | __half_as_ushort(h0);
            }
            uint4* d = (uint4*)(g_xg + (size_t)slot * IN_F + lane * 16);
            d[0] = make_uint4(H[0], H[1], H[2], H[3]);
            d[1] = make_uint4(H[4], H[5], H[6], H[7]);
        } else {
            // overflow token: zero its output row
            float4 z = make_float4(0.f, 0.f, 0.f, 0.f);
            float4* o = (float4*)(out + (size_t)(t0 + row) * OUT_F + lane * 16);
            o[0] = z; o[1] = z; o[2] = z; o[3] = z;
        }
    }
}

// ---------------- pre-pass: w -> fp16 ----------------
__global__ __launch_bounds__(256)
void k_cvt(const float* __restrict__ src, __half* __restrict__ dst, int n16) {
    int g = blockIdx.x * blockDim.x + threadIdx.x;
    if (g >= n16) return;
    const float4* s = (const float4*)(src + (size_t)g * 16);
    float4 v0 = s[0], v1 = s[1], v2 = s[2], v3 = s[3];
    float f[16] = {v0.x, v0.y, v0.z, v0.w, v1.x, v1.y, v1.z, v1.w,
                   v2.x, v2.y, v2.z, v2.w, v3.x, v3.y, v3.z, v3.w};
    uint32_t H[8];
#pragma unroll
    for (int j = 0; j < 8; j++) {
        __half h0 = __float2half_rn(f[2 * j]);
        __half h1 = __float2half_rn(f[2 * j + 1]);
        H[j] = ((uint32_t)__half_as_ushort(h1) << 16) | __half_as_ushort(h0);
    }
    uint4* d = (uint4*)(dst + (size_t)g * 16);
    d[0] = make_uint4(H[0], H[1], H[2], H[3]);
    d[1] = make_uint4(H[4], H[5], H[6], H[7]);
}

// ---------------- main GEMM: 128x64 tile, 256 threads, 2 CTAs/SM ----------------
__global__ __launch_bounds__(THREADS, 2)
void k_gemm(const float* __restrict__ bias, float* __restrict__ out) {
    extern __shared__ char smem[];

    const int e = blockIdx.y;
    int cnt = g_cnt[e];
    if (cnt > CAPACITY) cnt = CAPACITY;
    const int m0 = (blockIdx.x >> 3) * TM;
    if (m0 >= cnt) return;
    const int n0 = (blockIdx.x & 7) * TN;

    const int tid  = threadIdx.x;
    const int lane = tid & 31;
    const int wid  = tid >> 5;

    int*   stok  = (int*)(smem + SM_TOK);
    float* sbias = (float*)(smem + SM_BIAS);

    if (tid < TM) {
        stok[tid] = (m0 + tid < cnt) ? g_tok[e * CAPACITY + m0 + tid] : 0;
    } else if (tid < TM + TN) {
        sbias[tid - TM] = bias[e * OUT_F + n0 + (tid - TM)];
    }
    __syncthreads();

    const uint32_t sb = smem_u32(smem);
    const size_t xrow0 = (size_t)(e * CAPACITY + m0) * IN_F;
    const size_t wrow0 = ((size_t)e * OUT_F + n0) * IN_F;

    // cp.async: 1536 x 16B chunks per stage (X 1024 + W 512), 6 per thread
    auto issue = [&](int c, int st) {
        const uint32_t stg = sb + SM_BUF + st * STG_SZ;
        const int k0 = c * KC;
#pragma unroll
        for (int i = 0; i < 6; i++) {
            int g = tid + i * THREADS;              // 0..1535
            if (g < 1024) {
                int row = g >> 3, kg = g & 7;
                uint32_t dst = stg + SWZ((uint32_t)(row * 128 + kg * 16));
                cp16(dst, g_xg + xrow0 + (size_t)row * IN_F + k0 + kg * 8);
            } else {
                int gw = g - 1024;
                int row = gw >> 3, kg = gw & 7;
                uint32_t dst = stg + TILE_X + SWZ((uint32_t)(row * 128 + kg * 16));
                cp16(dst, g_wf + wrow0 + (size_t)row * IN_F + k0 + kg * 8);
            }
        }
        cp_commit();
    };

    // per-warp ldmatrix address precompute (stage-relative)
    const int aw = (wid & 3) * 32;   // warp M offset
    const int bw = (wid >> 2) * 32;  // warp N offset

    uint32_t a_off[2], a_mask[2];
    {
        int ar = lane & 15;
#pragma unroll
        for (int fi = 0; fi < 2; fi++) {
            int r = aw + fi * 16 + ar;
            a_off[fi] = (uint32_t)(r * 128);
            a_mask[fi] = (r & 7) * 16;
        }
    }
    const uint32_t a_klane = (lane & 16) ? 16u : 0u;

    uint32_t b_off[2], b_mask[2];
    {
        int br = (lane & 7) + ((lane & 16) ? 8 : 0);
#pragma unroll
        for (int jp = 0; jp < 2; jp++) {
            int r = bw + jp * 16 + br;
            b_off[jp] = (uint32_t)(TILE_X + r * 128);
            b_mask[jp] = (r & 7) * 16;
        }
    }
    const uint32_t b_klane = (lane & 8) ? 16u : 0u;

    float acc[2][4][4];
#pragma unroll
    for (int i = 0; i < 2; i++)
#pragma unroll
        for (int j = 0; j < 4; j++)
#pragma unroll
            for (int q = 0; q < 4; q++) acc[i][j][q] = 0.f;

    // ---- pipeline: 4 buffers, 3 chunks in flight ----
    issue(0, 0);
    issue(1, 1);
    issue(2, 2);

#pragma unroll
    for (int c = 0; c < NCH; c++) {
        if (c <= NCH - 3)      cp_wait<2>();
        else if (c == NCH - 2) cp_wait<1>();
        else                   cp_wait<0>();
        __syncthreads();   // stage c fully visible to all warps

        if (c + 3 < NCH) issue(c + 3, (c + 3) % NSTAGE);

        const uint32_t stg = sb + SM_BUF + (c % NSTAGE) * STG_SZ;

        // register-pipelined s-loop: load s+1's fragments before s's MMAs
        uint32_t xf[2][2][4], wf[2][2][4];
        {
#pragma unroll
            for (int fi = 0; fi < 2; fi++)
                ldsm4(xf[0][fi], stg + a_off[fi] + (a_klane ^ a_mask[fi]));
#pragma unroll
            for (int jp = 0; jp < 2; jp++)
                ldsm4(wf[0][jp], stg + b_off[jp] + (b_klane ^ b_mask[jp]));
        }
#pragma unroll
        for (int s = 0; s < 4; s++) {
            const int cur = s & 1, nxt = cur ^ 1;
            if (s < 3) {
                const uint32_t kcol = (uint32_t)((s + 1) * 32);
#pragma unroll
                for (int fi = 0; fi < 2; fi++)
                    ldsm4(xf[nxt][fi], stg + a_off[fi] + ((kcol + a_klane) ^ a_mask[fi]));
#pragma unroll
                for (int jp = 0; jp < 2; jp++)
                    ldsm4(wf[nxt][jp], stg + b_off[jp] + ((kcol + b_klane) ^ b_mask[jp]));
            }
#pragma unroll
            for (int fi = 0; fi < 2; fi++) {
#pragma unroll
                for (int j = 0; j < 4; j++) {
                    mma16816(acc[fi][j], xf[cur][fi], &wf[cur][j >> 1][(j & 1) * 2]);
                }
            }
        }
    }

    // ---- epilogue: stage acc through smem for coalesced scatter ----
    __syncthreads();
    float* sacc = (float*)(smem + SM_BUF);
    {
        const int r0 = aw + (lane >> 2);
        const int c0 = bw + 2 * (lane & 3);
#pragma unroll
        for (int fi = 0; fi < 2; fi++) {
#pragma unroll
            for (int j = 0; j < 4; j++) {
                int rr = r0 + fi * 16;
                int cc = c0 + j * 8;
                sacc[rr * ACCW + cc]           = acc[fi][j][0];
                sacc[rr * ACCW + cc + 1]       = acc[fi][j][1];
                sacc[(rr + 8) * ACCW + cc]     = acc[fi][j][2];
                sacc[(rr + 8) * ACCW + cc + 1] = acc[fi][j][3];
            }
        }
    }
    __syncthreads();

    {
        const int row = tid >> 1;                 // 0..127
        const int q   = (tid & 1) * 32;           // half of 64 cols
        if (m0 + row < cnt) {
            const int tok = stok[row];
            float* op = out + (size_t)tok * OUT_F + n0 + q;
            const float* sr = &sacc[row * ACCW + q];
#pragma unroll
            for (int i = 0; i < 8; i++) {
                float4 v = *(const float4*)(sr + i * 4);
                v.x += sbias[q + i * 4 + 0];
                v.y += sbias[q + i * 4 + 1];
                v.z += sbias[q + i * 4 + 2];
                v.w += sbias[q + i * 4 + 3];
                *(float4*)(op + i * 4) = v;
            }
        }
    }
}

// ---------------- launch ----------------
extern "C" void kernel_launch(void* const* d_in, const int* in_sizes, int n_in,
                              void* d_out, int out_size) {
    const float* x    = (const float*)d_in[0];
    const float* wght = (const float*)d_in[1];
    const float* bias = (const float*)d_in[2];
    const int*   eid  = (const int*)d_in[3];
    float* out = (float*)d_out;

    cudaFuncSetAttribute(k_gemm, cudaFuncAttributeMaxDynamicSharedMemorySize,
                         SMEM_TOTAL);

    __half* wf;
    cudaGetSymbolAddress((void**)&wf, g_wf);

    k_zero<<<1, 64>>>();
    k_route<<<NTOK / RBLK, RBLK>>>(x, eid, out);

    const int nw16 = NUM_E * OUT_F * IN_F / 16;      // 1048576
    k_cvt<<<nw16 / 256, 256>>>(wght, wf, nw16);

    dim3 grid(MTILES * NTILES, NUM_E);
    k_gemm<<<grid, THREADS, SMEM_TOTAL>>>(bias, out);
}